// round 3
// baseline (speedup 1.0000x reference)
#include <cuda_runtime.h>
#include <cstdint>
#define NN 3072
#define NSL 4
#define JSL (NN/NSL)

__device__ float g_wkeff[4*256], g_c1[4], g_skb[4];
__device__ float g_ek[NN*4];
__device__ float g_v[NN*256];
__device__ float g_part[(size_t)NSL*NN*256];
__device__ float g_Dp[(size_t)NSL*NN*4];
__device__ float g_msg[NN*256];
__device__ float g_o[NN*256];

__global__ void kprep0(const float* Wk, const float* bk, const float* Wew, const float* u){
    int m = threadIdx.x;
    for (int h=0;h<4;h++){
        float s=0.f;
        for (int d=0;d<64;d++) s += u[h*136+64+d]*Wk[(h*64+d)*256+m];
        g_wkeff[h*256+m]=s;
    }
    if (m<4){
        float c=0.f, sb=0.f;
        for (int d=0;d<8;d++)  c  += Wew[m*8+d]*u[m*136+128+d];
        for (int d=0;d<64;d++) sb += bk[m*64+d]*u[m*136+64+d];
        g_c1[m]=c; g_skb[m]=sb;
    }
}

__global__ void kprep1(const float* hm){
    __shared__ float wk[1024];
    int t = threadIdx.x;
    ((float4*)wk)[t] = ((const float4*)g_wkeff)[t];
    __syncthreads();
    int j = blockIdx.x*64 + (t>>2), ch = t&3;
    const float* hr = hm + (size_t)j*256;
    const float* w = wk + ch*256;
    float s = g_skb[ch];
    for (int m=0;m<256;m+=4){
        float4 hv = *(const float4*)(hr+m);
        s += hv.x*w[m]+hv.y*w[m+1]+hv.z*w[m+2]+hv.w*w[m+3];
    }
    g_ek[j*4+ch] = expf(s);
}

// C = A @ B^T + bias ; mode 0: A=arg,out=g_v ; mode 1: A=g_msg,out=g_o
__global__ __launch_bounds__(256) void kgemm(const float* A, const float* B, const float* bias, int mode){
    __shared__ float As[64][17], Bs[64][17];
    if (mode==1) A = g_msg;
    float* C = mode==1 ? g_o : g_v;
    int t=threadIdx.x, i0=blockIdx.x*64, c0=blockIdx.y*64;
    int tx=t&15, ty=t>>4, r=t>>2, k4=(t&3)*4;
    float acc[4][4]={};
    for (int k0=0;k0<256;k0+=16){
        float4 a=*(const float4*)(A+(size_t)(i0+r)*256+k0+k4);
        As[r][k4]=a.x;As[r][k4+1]=a.y;As[r][k4+2]=a.z;As[r][k4+3]=a.w;
        float4 b=*(const float4*)(B+(size_t)(c0+r)*256+k0+k4);
        Bs[r][k4]=b.x;Bs[r][k4+1]=b.y;Bs[r][k4+2]=b.z;Bs[r][k4+3]=b.w;
        __syncthreads();
        #pragma unroll
        for (int kk=0;kk<16;kk++){
            float av[4],bw[4];
            #pragma unroll
            for (int q=0;q<4;q++){ av[q]=As[ty*4+q][kk]; bw[q]=Bs[tx*4+q][kk]; }
            #pragma unroll
            for (int q=0;q<4;q++)
                #pragma unroll
                for (int p=0;p<4;p++) acc[q][p]=fmaf(av[q],bw[p],acc[q][p]);
        }
        __syncthreads();
    }
    for (int q=0;q<4;q++){
        int c=c0+tx*4;
        float4 o=make_float4(acc[q][0]+bias[c],acc[q][1]+bias[c+1],acc[q][2]+bias[c+2],acc[q][3]+bias[c+3]);
        *(float4*)(C+(size_t)(i0+ty*4+q)*256+c)=o;
    }
}

// partial msg over j-slice: 32 i-rows x 256 cols per block
__global__ __launch_bounds__(256) void kmain(const float* w){
    __shared__ float vs[16][260];
    __shared__ float cf[4][545];
    int t=threadIdx.x, i0=blockIdx.x*32, sl=blockIdx.y;
    int lane=t&31, wid=t>>5, cg=t&31, hh=cg>>3;
    float c1h[4]={g_c1[0],g_c1[1],g_c1[2],g_c1[3]};
    float acc[4][8]={}; float regD[2][4]={};
    for (int ch=0;ch<JSL/16;ch++){
        int j0 = sl*JSL + ch*16;
        #pragma unroll
        for (int q=0;q<4;q++){
            int idx=t+q*256, jj=idx>>6, cc=(idx&63)*4;
            *(float4*)&vs[jj][cc] = *(const float4*)(g_v+(size_t)(j0+jj)*256+cc);
        }
        #pragma unroll
        for (int q=0;q<2;q++){
            int jj=t&15, rr=(t>>4)+q*16;
            float x = w[(size_t)(i0+rr)*NN + j0+jj];
            float4 e4 = *(const float4*)(g_ek+(size_t)(j0+jj)*4);
            float ee[4]={e4.x,e4.y,e4.z,e4.w};
            bool mk = x>0.f;
            #pragma unroll
            for (int h=0;h<4;h++){
                float t1=x*c1h[h];
                float p=ee[h]*fmaf(t1,fmaf(t1,0.5f,1.f),1.f);
                cf[h][rr*17+jj] = mk? x*p : 0.f;
                if (mk) regD[q][h]+=p;
            }
        }
        __syncthreads();
        #pragma unroll 4
        for (int jj=0;jj<16;jj++){
            float4 v0=*(float4*)&vs[jj][cg*8], v1=*(float4*)&vs[jj][cg*8+4];
            #pragma unroll
            for (int rq=0;rq<4;rq++){
                float c=cf[hh][(wid*4+rq)*17+jj];
                acc[rq][0]=fmaf(c,v0.x,acc[rq][0]); acc[rq][1]=fmaf(c,v0.y,acc[rq][1]);
                acc[rq][2]=fmaf(c,v0.z,acc[rq][2]); acc[rq][3]=fmaf(c,v0.w,acc[rq][3]);
                acc[rq][4]=fmaf(c,v1.x,acc[rq][4]); acc[rq][5]=fmaf(c,v1.y,acc[rq][5]);
                acc[rq][6]=fmaf(c,v1.z,acc[rq][6]); acc[rq][7]=fmaf(c,v1.w,acc[rq][7]);
            }
        }
        __syncthreads();
    }
    #pragma unroll
    for (int rq=0;rq<4;rq++){
        float* dst=g_part+((size_t)sl*NN+i0+wid*4+rq)*256+cg*8;
        *(float4*)dst=make_float4(acc[rq][0],acc[rq][1],acc[rq][2],acc[rq][3]);
        *(float4*)(dst+4)=make_float4(acc[rq][4],acc[rq][5],acc[rq][6],acc[rq][7]);
    }
    #pragma unroll
    for (int q=0;q<2;q++){
        #pragma unroll
        for (int h=0;h<4;h++){
            float v=regD[q][h];
            for (int o=8;o;o>>=1) v+=__shfl_xor_sync(0xffffffffu,v,o);
            regD[q][h]=v;
        }
        if ((t&15)==0)
            *(float4*)(g_Dp+((size_t)sl*NN+i0+(t>>4)+q*16)*4)=
                make_float4(regD[q][0],regD[q][1],regD[q][2],regD[q][3]);
    }
}

__global__ void kreduce(){
    int i=blockIdx.x, c=threadIdx.x, h=c>>6;
    float D=0.f, s=0.f;
    for (int sl=0;sl<NSL;sl++){
        D += g_Dp[((size_t)sl*NN+i)*4+h];
        s += g_part[((size_t)sl*NN+i)*256+c];
    }
    g_msg[(size_t)i*256+c]=s/D;
}

__global__ void kln(const float* hm, const float* gamma, const float* beta, float* out){
    __shared__ float red[8];
    int i=blockIdx.x, t=threadIdx.x;
    float x = hm[(size_t)i*256+t] + g_o[(size_t)i*256+t];
    float v=x;
    for (int o=16;o;o>>=1) v+=__shfl_xor_sync(0xffffffffu,v,o);
    if ((t&31)==0) red[t>>5]=v;
    __syncthreads();
    if (t==0){ float s=0; for(int k=0;k<8;k++)s+=red[k]; red[0]=s*(1.f/256.f); }
    __syncthreads();
    float mu=red[0], d=x-mu;
    __syncthreads();
    v=d*d;
    for (int o=16;o;o>>=1) v+=__shfl_xor_sync(0xffffffffu,v,o);
    if ((t&31)==0) red[t>>5]=v;
    __syncthreads();
    if (t==0){ float s=0; for(int k=0;k<8;k++)s+=red[k]; red[0]=s*(1.f/256.f); }
    __syncthreads();
    out[(size_t)i*256+t] = gamma[t]*d*rsqrtf(red[0]+1e-5f)+beta[t];
}

extern "C" void kernel_launch(void* const* d_in, const int* in_sizes, int n_in,
                              void* d_out, int out_size){
    const float *hm=(const float*)d_in[0], *w=(const float*)d_in[1],
        *Wk=(const float*)d_in[4], *bk=(const float*)d_in[5],
        *Wv=(const float*)d_in[6], *bv=(const float*)d_in[7],
        *Wew=(const float*)d_in[8], *u=(const float*)d_in[10],
        *Wo=(const float*)d_in[11], *bo=(const float*)d_in[12],
        *gamma=(const float*)d_in[13], *beta=(const float*)d_in[14];
    kprep0<<<1,256>>>(Wk,bk,Wew,u);
    kprep1<<<48,256>>>(hm);
    kgemm<<<dim3(48,4),256>>>(hm,Wv,bv,0);
    kmain<<<dim3(96,NSL),256>>>(w);
    kreduce<<<NN,256>>>();
    kgemm<<<dim3(48,4),256>>>(nullptr,Wo,bo,1);
    kln<<<NN,256>>>(hm,gamma,beta,(float*)d_out);
}

// round 10
// speedup vs baseline: 1.9704x; 1.9704x over previous
#include <cuda_runtime.h>
#include <cuda_bf16.h>
#include <cstdint>
#define NN 3072
#define KK 6144
#define NSL 6

__device__ __align__(256) float g_wkeff[4*256];
__device__ float g_c1[4], g_skb[4];
__device__ __align__(256) float g_ek[NN*4];
__device__ __align__(256) float g_v[NN*256];
__device__ __align__(256) __nv_bfloat16 g_A[(size_t)NN*KK];
__device__ __align__(256) __nv_bfloat16 g_Bt[(size_t)256*KK];
__device__ __align__(256) float g_part[(size_t)NSL*NN*256];
__device__ __align__(256) float g_D[NN*4];
__device__ __align__(256) float g_msg[NN*256];
__device__ __align__(256) float g_o[NN*256];

__device__ __forceinline__ uint32_t s2u(const void* p){
    uint32_t a; asm("{.reg .u64 t; cvta.to.shared.u64 t, %1; cvt.u32.u64 %0, t;}":"=r"(a):"l"(p)); return a;
}
__device__ __forceinline__ void ldm4(uint32_t* r, uint32_t a){
    asm volatile("ldmatrix.sync.aligned.m8n8.x4.shared.b16 {%0,%1,%2,%3},[%4];"
        :"=r"(r[0]),"=r"(r[1]),"=r"(r[2]),"=r"(r[3]):"r"(a));
}
__device__ __forceinline__ void mma16816(float* c, const uint32_t* a, uint32_t b0, uint32_t b1){
    asm volatile("mma.sync.aligned.m16n8k16.row.col.f32.bf16.bf16.f32 "
        "{%0,%1,%2,%3},{%4,%5,%6,%7},{%8,%9},{%0,%1,%2,%3};"
        :"+f"(c[0]),"+f"(c[1]),"+f"(c[2]),"+f"(c[3])
        :"r"(a[0]),"r"(a[1]),"r"(a[2]),"r"(a[3]),"r"(b0),"r"(b1));
}

__global__ void kprep0(const float* Wk, const float* bk, const float* Wew, const float* u){
    int m = threadIdx.x;
    for (int h=0;h<4;h++){
        float s=0.f;
        for (int d=0;d<64;d++) s += u[h*136+64+d]*Wk[(h*64+d)*256+m];
        g_wkeff[h*256+m]=s;
    }
    if (m<4){
        float c=0.f, sb=0.f;
        for (int d=0;d<8;d++)  c  += Wew[m*8+d]*u[m*136+128+d];
        for (int d=0;d<64;d++) sb += bk[m*64+d]*u[m*136+64+d];
        g_c1[m]=c; g_skb[m]=sb;
    }
}

__global__ void kprep1(const float* hm){
    __shared__ __align__(16) float wk[1024];
    int t = threadIdx.x;
    ((float4*)wk)[t] = ((const float4*)g_wkeff)[t];
    __syncthreads();
    int j = blockIdx.x*64 + (t>>2), ch = t&3;
    const float* hr = hm + (size_t)j*256;
    const float* w = wk + ch*256;
    float s = g_skb[ch];
    for (int m=0;m<256;m+=4){
        float4 hv = *(const float4*)(hr+m);
        s += hv.x*w[m]+hv.y*w[m+1]+hv.z*w[m+2]+hv.w*w[m+3];
    }
    g_ek[j*4+ch] = expf(s);
}

__global__ __launch_bounds__(256) void kgemm(const float* A, const float* B, const float* bias, int mode){
    __shared__ __align__(16) float As[64][17], Bs[64][17];
    if (mode==1) A = g_msg;
    float* C = mode==1 ? g_o : g_v;
    int t=threadIdx.x, i0=blockIdx.x*64, c0=blockIdx.y*64;
    int tx=t&15, ty=t>>4, r=t>>2, k4=(t&3)*4;
    float acc[4][4]={};
    for (int k0=0;k0<256;k0+=16){
        float4 a=*(const float4*)(A+(size_t)(i0+r)*256+k0+k4);
        As[r][k4]=a.x;As[r][k4+1]=a.y;As[r][k4+2]=a.z;As[r][k4+3]=a.w;
        float4 b=*(const float4*)(B+(size_t)(c0+r)*256+k0+k4);
        Bs[r][k4]=b.x;Bs[r][k4+1]=b.y;Bs[r][k4+2]=b.z;Bs[r][k4+3]=b.w;
        __syncthreads();
        #pragma unroll
        for (int kk=0;kk<16;kk++){
            float av[4],bw[4];
            #pragma unroll
            for (int q=0;q<4;q++){ av[q]=As[ty*4+q][kk]; bw[q]=Bs[tx*4+q][kk]; }
            #pragma unroll
            for (int q=0;q<4;q++)
                #pragma unroll
                for (int p=0;p<4;p++) acc[q][p]=fmaf(av[q],bw[p],acc[q][p]);
        }
        __syncthreads();
    }
    for (int q=0;q<4;q++){
        int c=c0+tx*4;
        float4 o=make_float4(acc[q][0]+bias[c],acc[q][1]+bias[c+1],acc[q][2]+bias[c+2],acc[q][3]+bias[c+3]);
        *(float4*)(C+(size_t)(i0+ty*4+q)*256+c)=o;
    }
}

// A phys: [0,3072)=w (masked, bf16), [3072,6144)=w^2. D[i][h] exact fp32.
__global__ __launch_bounds__(256) void kpow(const float* w){
    __shared__ __align__(16) float es[NN*4];
    int t=threadIdx.x;
    for (int q=0;q<12;q++) ((float4*)es)[t+q*256] = ((const float4*)g_ek)[t+q*256];
    __syncthreads();
    float c1h[4]={g_c1[0],g_c1[1],g_c1[2],g_c1[3]};
    int i = blockIdx.x*8 + (t>>5), l = t&31;
    const float* wr = w + (size_t)i*NN;
    __nv_bfloat16* Ar = g_A + (size_t)i*KK;
    float D0=0,D1=0,D2=0,D3=0;
    for (int k=0;k<24;k++){
        int j = k*128 + l*4;
        float4 wv = *(const float4*)(wr+j);
        float xs[4]={wv.x,wv.y,wv.z,wv.w};
        __nv_bfloat16 hi[4], sq[4];
        #pragma unroll
        for (int e=0;e<4;e++){
            float x = xs[e]; bool mk = x>0.f;
            float a = mk? x:0.f;
            hi[e]=__float2bfloat16_rn(a);
            sq[e]=__float2bfloat16_rn(a*x);
            if (mk){
                const float* er = es + (j+e)*4;
                D0 = fmaf(x, c1h[0]*er[0], D0+er[0]);
                D1 = fmaf(x, c1h[1]*er[1], D1+er[1]);
                D2 = fmaf(x, c1h[2]*er[2], D2+er[2]);
                D3 = fmaf(x, c1h[3]*er[3], D3+er[3]);
            }
        }
        *(uint2*)(Ar+j)      = *(uint2*)hi;
        *(uint2*)(Ar+3072+j) = *(uint2*)sq;
    }
    for (int o=16;o;o>>=1){
        D0+=__shfl_xor_sync(~0u,D0,o); D1+=__shfl_xor_sync(~0u,D1,o);
        D2+=__shfl_xor_sync(~0u,D2,o); D3+=__shfl_xor_sync(~0u,D3,o);
    }
    if (l==0) *(float4*)(g_D+i*4)=make_float4(D0,D1,D2,D3);
}

// Bt[c]: [0,3072)=V1=ek*v, [3072,6144)=V2=c1*V1
__global__ __launch_bounds__(256) void kbuild(){
    __shared__ __align__(16) float vs[64][68];
    __shared__ __align__(16) float es[64][4];
    int t=threadIdx.x, j0=blockIdx.x*64, c0=blockIdx.y*64;
    #pragma unroll
    for (int r=0;r<4;r++){
        int idx=t+r*256, row=idx>>4, col=(idx&15)*4;
        *(float4*)&vs[row][col] = *(const float4*)(g_v+(size_t)(j0+row)*256+c0+col);
    }
    if (t<64) *(float4*)es[t] = *(const float4*)(g_ek+(size_t)(j0+t)*4);
    __syncthreads();
    int cl=t>>2, jq=t&3, c=c0+cl, h=c>>6;
    float c1h=g_c1[h];
    __nv_bfloat16 bh[16], b2[16];
    #pragma unroll
    for (int jj=0;jj<16;jj++){
        int jl=jq*16+jj;
        float V1 = es[jl][h]*vs[jl][cl];
        bh[jj]=__float2bfloat16_rn(V1);
        b2[jj]=__float2bfloat16_rn(c1h*V1);
    }
    __nv_bfloat16* Br = g_Bt + (size_t)c*KK + j0 + jq*16;
    *(uint4*)(Br)      = *(uint4*)(bh);  *(uint4*)(Br+8)      = *(uint4*)(bh+8);
    *(uint4*)(Br+3072) = *(uint4*)(b2);  *(uint4*)(Br+3072+8) = *(uint4*)(b2+8);
}

// bf16 HMMA GEMM: part[sl][i][c] = sum_{k in slice} A[i][k]*Bt[c][k]; ka==kb==kl (identity map)
__global__ __launch_bounds__(256,2) void kmma(){
    __shared__ __align__(16) __nv_bfloat16 Asm[2][128*40];
    __shared__ __align__(16) __nv_bfloat16 Bsm[2][128*40];
    const int tid=threadIdx.x, lane=tid&31, wid=tid>>5;
    const int wm=wid&3, wn=wid>>2;
    const int i0=blockIdx.x*128, c0=blockIdx.y*128, sl=blockIdx.z;
    float acc[2][8][4];
    #pragma unroll
    for(int a=0;a<2;a++)
        #pragma unroll
        for(int b=0;b<8;b++)
            #pragma unroll
            for(int c=0;c<4;c++) acc[a][b][c]=0.f;
    const int r4 = tid>>2, q4 = (tid&3)*8;
    const int arow = lane&15, akh = (lane>>4)*8;
    const int brow = (lane&7) + ((lane>>4)&1)*8, bkh = ((lane>>3)&1)*8;
    auto ld_stage=[&](int buf,int st){
        int kl = sl*1024 + st*32;
        #pragma unroll
        for(int hh=0;hh<2;hh++){
            int row=r4+hh*64;
            uint32_t da = s2u(&Asm[buf][row*40+q4]);
            const void* sa = g_A + (size_t)(i0+row)*KK + kl + q4;
            asm volatile("cp.async.cg.shared.global [%0],[%1],16;"::"r"(da),"l"(sa));
            uint32_t db = s2u(&Bsm[buf][row*40+q4]);
            const void* sb = g_Bt + (size_t)(c0+row)*KK + kl + q4;
            asm volatile("cp.async.cg.shared.global [%0],[%1],16;"::"r"(db),"l"(sb));
        }
        asm volatile("cp.async.commit_group;");
    };
    ld_stage(0,0);
    for(int st=0;st<32;st++){
        int buf=st&1;
        if(st<31){ ld_stage(buf^1,st+1); asm volatile("cp.async.wait_group 1;"); }
        else { asm volatile("cp.async.wait_group 0;"); }
        __syncthreads();
        uint32_t abase = s2u(&Asm[buf][0]), bbase = s2u(&Bsm[buf][0]);
        #pragma unroll
        for(int kk=0;kk<2;kk++){
            uint32_t af[2][4], bf[4][4];
            #pragma unroll
            for(int mb=0;mb<2;mb++)
                ldm4(af[mb], abase + (uint32_t)((wm*32+mb*16+arow)*40 + kk*16 + akh)*2u);
            #pragma unroll
            for(int nb=0;nb<4;nb++)
                ldm4(bf[nb], bbase + (uint32_t)((wn*64+nb*16+brow)*40 + kk*16 + bkh)*2u);
            #pragma unroll
            for(int mb=0;mb<2;mb++)
                #pragma unroll
                for(int nb=0;nb<4;nb++){
                    mma16816(acc[mb][nb*2],   af[mb], bf[nb][0], bf[nb][1]);
                    mma16816(acc[mb][nb*2+1], af[mb], bf[nb][2], bf[nb][3]);
                }
        }
        __syncthreads();
    }
    #pragma unroll
    for(int mb=0;mb<2;mb++){
        int ri = i0 + wm*32 + mb*16 + (lane>>2);
        #pragma unroll
        for(int nbk=0;nbk<8;nbk++){
            int c = c0 + wn*64 + nbk*8 + (lane&3)*2;
            *(float2*)(g_part + ((size_t)sl*NN + ri)*256 + c)   = make_float2(acc[mb][nbk][0],acc[mb][nbk][1]);
            *(float2*)(g_part + ((size_t)sl*NN + ri+8)*256 + c) = make_float2(acc[mb][nbk][2],acc[mb][nbk][3]);
        }
    }
}

__global__ void kreduce(){
    int i=blockIdx.x, c=threadIdx.x, h=c>>6;
    float s=0.f;
    for (int sl=0;sl<NSL;sl++) s += g_part[((size_t)sl*NN+i)*256+c];
    g_msg[(size_t)i*256+c] = s / g_D[i*4+h];
}

__global__ void kln(const float* hm, const float* gamma, const float* beta, float* out){
    __shared__ float red[8];
    int i=blockIdx.x, t=threadIdx.x;
    float x = hm[(size_t)i*256+t] + g_o[(size_t)i*256+t];
    float v=x;
    for (int o=16;o;o>>=1) v+=__shfl_xor_sync(~0u,v,o);
    if ((t&31)==0) red[t>>5]=v;
    __syncthreads();
    if (t==0){ float s=0; for(int k=0;k<8;k++)s+=red[k]; red[0]=s*(1.f/256.f); }
    __syncthreads();
    float mu=red[0], d=x-mu;
    __syncthreads();
    v=d*d;
    for (int o=16;o;o>>=1) v+=__shfl_xor_sync(~0u,v,o);
    if ((t&31)==0) red[t>>5]=v;
    __syncthreads();
    if (t==0){ float s=0; for(int k=0;k<8;k++)s+=red[k]; red[0]=s*(1.f/256.f); }
    __syncthreads();
    out[(size_t)i*256+t] = gamma[t]*d*rsqrtf(red[0]+1e-5f)+beta[t];
}

extern "C" void kernel_launch(void* const* d_in, const int* in_sizes, int n_in,
                              void* d_out, int out_size){
    const float *hm=(const float*)d_in[0], *w=(const float*)d_in[1],
        *Wk=(const float*)d_in[4], *bk=(const float*)d_in[5],
        *Wv=(const float*)d_in[6], *bv=(const float*)d_in[7],
        *Wew=(const float*)d_in[8], *u=(const float*)d_in[10],
        *Wo=(const float*)d_in[11], *bo=(const float*)d_in[12],
        *gamma=(const float*)d_in[13], *beta=(const float*)d_in[14];
    kprep0<<<1,256>>>(Wk,bk,Wew,u);
    kprep1<<<48,256>>>(hm);
    kgemm<<<dim3(48,4),256>>>(hm,Wv,bv,0);
    kpow<<<384,256>>>(w);
    kbuild<<<dim3(48,4),256>>>();
    kmma<<<dim3(24,2,NSL),256>>>();
    kreduce<<<NN,256>>>();
    kgemm<<<dim3(48,4),256>>>(nullptr,Wo,bo,1);
    kln<<<NN,256>>>(hm,gamma,beta,(float*)d_out);
}

// round 12
// speedup vs baseline: 1.9752x; 1.0024x over previous
#include <cuda_runtime.h>
#include <cuda_bf16.h>
#include <cstdint>
#define NN 3072
#define KK 6144
#define NSL 6
#define STG_BYTES 20480

__device__ __align__(256) float g_wkeff[4*256];
__device__ float g_c1[4], g_skb[4];
__device__ __align__(256) float g_ek[NN*4];
__device__ __align__(256) float g_v[NN*256];
__device__ __align__(256) __nv_bfloat16 g_A[(size_t)NN*KK];
__device__ __align__(256) __nv_bfloat16 g_Bt[(size_t)256*KK];
__device__ __align__(256) float g_part[(size_t)NSL*NN*256];
__device__ __align__(256) float g_D[NN*4];
__device__ __align__(256) float g_msg[NN*256];
__device__ __align__(256) float g_o[NN*256];

__device__ __forceinline__ uint32_t s2u(const void* p){
    uint32_t a; asm("{.reg .u64 t; cvta.to.shared.u64 t, %1; cvt.u32.u64 %0, t;}":"=r"(a):"l"(p)); return a;
}
__device__ __forceinline__ void ldm4(uint32_t* r, uint32_t a){
    asm volatile("ldmatrix.sync.aligned.m8n8.x4.shared.b16 {%0,%1,%2,%3},[%4];"
        :"=r"(r[0]),"=r"(r[1]),"=r"(r[2]),"=r"(r[3]):"r"(a));
}
__device__ __forceinline__ void mma16816(float* c, const uint32_t* a, uint32_t b0, uint32_t b1){
    asm volatile("mma.sync.aligned.m16n8k16.row.col.f32.bf16.bf16.f32 "
        "{%0,%1,%2,%3},{%4,%5,%6,%7},{%8,%9},{%0,%1,%2,%3};"
        :"+f"(c[0]),"+f"(c[1]),"+f"(c[2]),"+f"(c[3])
        :"r"(a[0]),"r"(a[1]),"r"(a[2]),"r"(a[3]),"r"(b0),"r"(b1));
}
template<int N> __device__ __forceinline__ void waitg(){
    asm volatile("cp.async.wait_group %0;"::"n"(N):"memory");
}

__global__ void kprep0(const float* Wk, const float* bk, const float* Wew, const float* u){
    int m = threadIdx.x;
    for (int h=0;h<4;h++){
        float s=0.f;
        for (int d=0;d<64;d++) s += u[h*136+64+d]*Wk[(h*64+d)*256+m];
        g_wkeff[h*256+m]=s;
    }
    if (m<4){
        float c=0.f, sb=0.f;
        for (int d=0;d<8;d++)  c  += Wew[m*8+d]*u[m*136+128+d];
        for (int d=0;d<64;d++) sb += bk[m*64+d]*u[m*136+64+d];
        g_c1[m]=c; g_skb[m]=sb;
    }
}

__global__ void kprep1(const float* hm){
    __shared__ __align__(16) float wk[1024];
    int t = threadIdx.x;
    ((float4*)wk)[t] = ((const float4*)g_wkeff)[t];
    __syncthreads();
    int j = blockIdx.x*64 + (t>>2), ch = t&3;
    const float* hr = hm + (size_t)j*256;
    const float* w = wk + ch*256;
    float s = g_skb[ch];
    for (int m=0;m<256;m+=4){
        float4 hv = *(const float4*)(hr+m);
        s += hv.x*w[m]+hv.y*w[m+1]+hv.z*w[m+2]+hv.w*w[m+3];
    }
    g_ek[j*4+ch] = expf(s);
}

__global__ __launch_bounds__(256) void kgemm(const float* A, const float* B, const float* bias, int mode){
    __shared__ __align__(16) float As[64][17], Bs[64][17];
    if (mode==1) A = g_msg;
    float* C = mode==1 ? g_o : g_v;
    int t=threadIdx.x, i0=blockIdx.x*64, c0=blockIdx.y*64;
    int tx=t&15, ty=t>>4, r=t>>2, k4=(t&3)*4;
    float acc[4][4]={};
    for (int k0=0;k0<256;k0+=16){
        float4 a=*(const float4*)(A+(size_t)(i0+r)*256+k0+k4);
        As[r][k4]=a.x;As[r][k4+1]=a.y;As[r][k4+2]=a.z;As[r][k4+3]=a.w;
        float4 b=*(const float4*)(B+(size_t)(c0+r)*256+k0+k4);
        Bs[r][k4]=b.x;Bs[r][k4+1]=b.y;Bs[r][k4+2]=b.z;Bs[r][k4+3]=b.w;
        __syncthreads();
        #pragma unroll
        for (int kk=0;kk<16;kk++){
            float av[4],bw[4];
            #pragma unroll
            for (int q=0;q<4;q++){ av[q]=As[ty*4+q][kk]; bw[q]=Bs[tx*4+q][kk]; }
            #pragma unroll
            for (int q=0;q<4;q++)
                #pragma unroll
                for (int p=0;p<4;p++) acc[q][p]=fmaf(av[q],bw[p],acc[q][p]);
        }
        __syncthreads();
    }
    for (int q=0;q<4;q++){
        int c=c0+tx*4;
        float4 o=make_float4(acc[q][0]+bias[c],acc[q][1]+bias[c+1],acc[q][2]+bias[c+2],acc[q][3]+bias[c+3]);
        *(float4*)(C+(size_t)(i0+ty*4+q)*256+c)=o;
    }
}

// A phys: [0,3072)=w (masked, bf16), [3072,6144)=w^2. D[i][h] exact fp32.
// No smem staging: g_ek reads hit L1/L2 (48KB, coalesced 16B/lane).
__global__ __launch_bounds__(256) void kpow(const float* w){
    int t=threadIdx.x;
    float c1h[4]={g_c1[0],g_c1[1],g_c1[2],g_c1[3]};
    int i = blockIdx.x*8 + (t>>5), l = t&31;
    const float* wr = w + (size_t)i*NN;
    __nv_bfloat16* Ar = g_A + (size_t)i*KK;
    float D0=0,D1=0,D2=0,D3=0;
    #pragma unroll 2
    for (int k=0;k<24;k++){
        int j = k*128 + l*4;
        float4 wv = *(const float4*)(wr+j);
        float xs[4]={wv.x,wv.y,wv.z,wv.w};
        __nv_bfloat16 hi[4], sq[4];
        #pragma unroll
        for (int e=0;e<4;e++){
            float x = xs[e]; bool mk = x>0.f;
            float a = mk? x:0.f;
            hi[e]=__float2bfloat16_rn(a);
            sq[e]=__float2bfloat16_rn(a*x);
            float4 er = __ldg((const float4*)(g_ek+(size_t)(j+e)*4));
            if (mk){
                D0 = fmaf(x, c1h[0]*er.x, D0+er.x);
                D1 = fmaf(x, c1h[1]*er.y, D1+er.y);
                D2 = fmaf(x, c1h[2]*er.z, D2+er.z);
                D3 = fmaf(x, c1h[3]*er.w, D3+er.w);
            }
        }
        *(uint2*)(Ar+j)      = *(uint2*)hi;
        *(uint2*)(Ar+3072+j) = *(uint2*)sq;
    }
    for (int o=16;o;o>>=1){
        D0+=__shfl_xor_sync(~0u,D0,o); D1+=__shfl_xor_sync(~0u,D1,o);
        D2+=__shfl_xor_sync(~0u,D2,o); D3+=__shfl_xor_sync(~0u,D3,o);
    }
    if (l==0) *(float4*)(g_D+i*4)=make_float4(D0,D1,D2,D3);
}

// Bt[c]: [0,3072)=V1=ek*v, [3072,6144)=V2=c1*V1
__global__ __launch_bounds__(256) void kbuild(){
    __shared__ __align__(16) float vs[64][68];
    __shared__ __align__(16) float es[64][4];
    int t=threadIdx.x, j0=blockIdx.x*64, c0=blockIdx.y*64;
    #pragma unroll
    for (int r=0;r<4;r++){
        int idx=t+r*256, row=idx>>4, col=(idx&15)*4;
        *(float4*)&vs[row][col] = *(const float4*)(g_v+(size_t)(j0+row)*256+c0+col);
    }
    if (t<64) *(float4*)es[t] = *(const float4*)(g_ek+(size_t)(j0+t)*4);
    __syncthreads();
    int cl=t>>2, jq=t&3, c=c0+cl, h=c>>6;
    float c1h=g_c1[h];
    __nv_bfloat16 bh[16], b2[16];
    #pragma unroll
    for (int jj=0;jj<16;jj++){
        int jl=jq*16+jj;
        float V1 = es[jl][h]*vs[jl][cl];
        bh[jj]=__float2bfloat16_rn(V1);
        b2[jj]=__float2bfloat16_rn(c1h*V1);
    }
    __nv_bfloat16* Br = g_Bt + (size_t)c*KK + j0 + jq*16;
    *(uint4*)(Br)      = *(uint4*)(bh);  *(uint4*)(Br+8)      = *(uint4*)(bh+8);
    *(uint4*)(Br+3072) = *(uint4*)(b2);  *(uint4*)(Br+3072+8) = *(uint4*)(b2+8);
}

// bf16 HMMA GEMM, 4-stage cp.async pipeline (dynamic smem, 80KB)
__global__ __launch_bounds__(256,2) void kmma(){
    extern __shared__ __align__(16) char smx[];
    const int tid=threadIdx.x, lane=tid&31, wid=tid>>5;
    const int wm=wid&3, wn=wid>>2;
    const int i0=blockIdx.x*128, c0=blockIdx.y*128, sl=blockIdx.z;
    float acc[2][8][4];
    #pragma unroll
    for(int a=0;a<2;a++)
        #pragma unroll
        for(int b=0;b<8;b++)
            #pragma unroll
            for(int c=0;c<4;c++) acc[a][b][c]=0.f;
    const int r4 = tid>>2, q4 = (tid&3)*8;
    const int arow = lane&15, akh = (lane>>4)*8;
    const int brow = (lane&7) + ((lane>>4)&1)*8, bkh = ((lane>>3)&1)*8;
    auto ld_stage=[&](int buf,int st){
        int kl = sl*1024 + st*32;
        char* base = smx + buf*STG_BYTES;
        #pragma unroll
        for(int hh=0;hh<2;hh++){
            int row=r4+hh*64;
            uint32_t da = s2u(base + (row*40+q4)*2);
            const void* sa = g_A + (size_t)(i0+row)*KK + kl + q4;
            asm volatile("cp.async.cg.shared.global [%0],[%1],16;"::"r"(da),"l"(sa));
            uint32_t db = s2u(base + 10240 + (row*40+q4)*2);
            const void* sb = g_Bt + (size_t)(c0+row)*KK + kl + q4;
            asm volatile("cp.async.cg.shared.global [%0],[%1],16;"::"r"(db),"l"(sb));
        }
        asm volatile("cp.async.commit_group;");
    };
    ld_stage(0,0); ld_stage(1,1); ld_stage(2,2);
    for(int st=0;st<32;st++){
        int buf=st&3;
        if(st+3<32) ld_stage((st+3)&3, st+3);
        if(st<29) waitg<3>();
        else if(st==29) waitg<2>();
        else if(st==30) waitg<1>();
        else waitg<0>();
        __syncthreads();
        char* base = smx + buf*STG_BYTES;
        uint32_t abase = s2u(base), bbase = s2u(base+10240);
        #pragma unroll
        for(int kk=0;kk<2;kk++){
            uint32_t af[2][4], bf[4][4];
            #pragma unroll
            for(int mb=0;mb<2;mb++)
                ldm4(af[mb], abase + (uint32_t)((wm*32+mb*16+arow)*40 + kk*16 + akh)*2u);
            #pragma unroll
            for(int nb=0;nb<4;nb++)
                ldm4(bf[nb], bbase + (uint32_t)((wn*64+nb*16+brow)*40 + kk*16 + bkh)*2u);
            #pragma unroll
            for(int mb=0;mb<2;mb++)
                #pragma unroll
                for(int nb=0;nb<4;nb++){
                    mma16816(acc[mb][nb*2],   af[mb], bf[nb][0], bf[nb][1]);
                    mma16816(acc[mb][nb*2+1], af[mb], bf[nb][2], bf[nb][3]);
                }
        }
        __syncthreads();
    }
    #pragma unroll
    for(int mb=0;mb<2;mb++){
        int ri = i0 + wm*32 + mb*16 + (lane>>2);
        #pragma unroll
        for(int nbk=0;nbk<8;nbk++){
            int c = c0 + wn*64 + nbk*8 + (lane&3)*2;
            *(float2*)(g_part + ((size_t)sl*NN + ri)*256 + c)   = make_float2(acc[mb][nbk][0],acc[mb][nbk][1]);
            *(float2*)(g_part + ((size_t)sl*NN + ri+8)*256 + c) = make_float2(acc[mb][nbk][2],acc[mb][nbk][3]);
        }
    }
}

__global__ void kreduce(){
    int i=blockIdx.x, c=threadIdx.x, h=c>>6;
    float s=0.f;
    for (int sl=0;sl<NSL;sl++) s += g_part[((size_t)sl*NN+i)*256+c];
    g_msg[(size_t)i*256+c] = s / g_D[i*4+h];
}

__global__ void kln(const float* hm, const float* gamma, const float* beta, float* out){
    __shared__ float red[8];
    int i=blockIdx.x, t=threadIdx.x;
    float x = hm[(size_t)i*256+t] + g_o[(size_t)i*256+t];
    float v=x;
    for (int o=16;o;o>>=1) v+=__shfl_xor_sync(~0u,v,o);
    if ((t&31)==0) red[t>>5]=v;
    __syncthreads();
    if (t==0){ float s=0; for(int k=0;k<8;k++)s+=red[k]; red[0]=s*(1.f/256.f); }
    __syncthreads();
    float mu=red[0], d=x-mu;
    __syncthreads();
    v=d*d;
    for (int o=16;o;o>>=1) v+=__shfl_xor_sync(~0u,v,o);
    if ((t&31)==0) red[t>>5]=v;
    __syncthreads();
    if (t==0){ float s=0; for(int k=0;k<8;k++)s+=red[k]; red[0]=s*(1.f/256.f); }
    __syncthreads();
    out[(size_t)i*256+t] = gamma[t]*d*rsqrtf(red[0]+1e-5f)+beta[t];
}

extern "C" void kernel_launch(void* const* d_in, const int* in_sizes, int n_in,
                              void* d_out, int out_size){
    const float *hm=(const float*)d_in[0], *w=(const float*)d_in[1],
        *Wk=(const float*)d_in[4], *bk=(const float*)d_in[5],
        *Wv=(const float*)d_in[6], *bv=(const float*)d_in[7],
        *Wew=(const float*)d_in[8], *u=(const float*)d_in[10],
        *Wo=(const float*)d_in[11], *bo=(const float*)d_in[12],
        *gamma=(const float*)d_in[13], *beta=(const float*)d_in[14];
    cudaFuncSetAttribute(kmma, cudaFuncAttributeMaxDynamicSharedMemorySize, 4*STG_BYTES);
    kprep0<<<1,256>>>(Wk,bk,Wew,u);
    kprep1<<<48,256>>>(hm);
    kgemm<<<dim3(48,4),256>>>(hm,Wv,bv,0);
    kpow<<<384,256>>>(w);
    kbuild<<<dim3(48,4),256>>>();
    kmma<<<dim3(24,2,NSL),256,4*STG_BYTES>>>();
    kreduce<<<NN,256>>>();
    kgemm<<<dim3(48,4),256>>>(nullptr,Wo,bo,1);
    kln<<<NN,256>>>(hm,gamma,beta,(float*)d_out);
}

// round 15
// speedup vs baseline: 2.1690x; 1.0981x over previous
#include <cuda_runtime.h>
#include <cuda_bf16.h>
#include <cstdint>
#define NN 3072
#define KK 6144
#define NSL 6
#define STG_BYTES 20480

__device__ __align__(256) float g_wkeff[4*256];
__device__ float g_c1[4], g_skb[4];
__device__ __align__(256) float g_ek[NN*4];
__device__ __align__(256) float g_v[NN*256];
__device__ __align__(256) __nv_bfloat16 g_A[(size_t)NN*KK];
__device__ __align__(256) __nv_bfloat16 g_Bt[(size_t)256*KK];
__device__ __align__(256) float g_part[(size_t)NSL*NN*256];
__device__ __align__(256) float g_Dp[2*NN*4];
__device__ __align__(256) float g_msg[NN*256];
__device__ __align__(256) float g_o[NN*256];

__device__ __forceinline__ uint32_t s2u(const void* p){
    uint32_t a; asm("{.reg .u64 t; cvta.to.shared.u64 t, %1; cvt.u32.u64 %0, t;}":"=r"(a):"l"(p)); return a;
}
__device__ __forceinline__ void ldm4(uint32_t* r, uint32_t a){
    asm volatile("ldmatrix.sync.aligned.m8n8.x4.shared.b16 {%0,%1,%2,%3},[%4];"
        :"=r"(r[0]),"=r"(r[1]),"=r"(r[2]),"=r"(r[3]):"r"(a));
}
__device__ __forceinline__ void mma16816(float* c, const uint32_t* a, uint32_t b0, uint32_t b1){
    asm volatile("mma.sync.aligned.m16n8k16.row.col.f32.bf16.bf16.f32 "
        "{%0,%1,%2,%3},{%4,%5,%6,%7},{%8,%9},{%0,%1,%2,%3};"
        :"+f"(c[0]),"+f"(c[1]),"+f"(c[2]),"+f"(c[3])
        :"r"(a[0]),"r"(a[1]),"r"(a[2]),"r"(a[3]),"r"(b0),"r"(b1));
}
template<int N> __device__ __forceinline__ void waitg(){
    asm volatile("cp.async.wait_group %0;"::"n"(N):"memory");
}

// grid 4: block = head h
__global__ void kprep0(const float* Wk, const float* bk, const float* Wew, const float* u){
    int m = threadIdx.x, h = blockIdx.x;
    float s=0.f;
    for (int d=0;d<64;d++) s += u[h*136+64+d]*Wk[(h*64+d)*256+m];
    g_wkeff[h*256+m]=s;
    if (m==0){
        float c=0.f, sb=0.f;
        for (int d=0;d<8;d++)  c  += Wew[h*8+d]*u[h*136+128+d];
        for (int d=0;d<64;d++) sb += bk[h*64+d]*u[h*136+64+d];
        g_c1[h]=c; g_skb[h]=sb;
    }
}

__global__ void kprep1(const float* hm){
    __shared__ __align__(16) float wk[1024];
    int t = threadIdx.x;
    ((float4*)wk)[t] = ((const float4*)g_wkeff)[t];
    __syncthreads();
    int j = blockIdx.x*64 + (t>>2), ch = t&3;
    const float* hr = hm + (size_t)j*256;
    const float* w = wk + ch*256;
    float s = g_skb[ch];
    for (int m=0;m<256;m+=4){
        float4 hv = *(const float4*)(hr+m);
        s += hv.x*w[m]+hv.y*w[m+1]+hv.z*w[m+2]+hv.w*w[m+3];
    }
    g_ek[j*4+ch] = expf(s);
}

// C = A@B^T + bias; smem transposed [kk][row] -> LDS.128 reads
__global__ __launch_bounds__(256) void kgemm(const float* A, const float* B, const float* bias, int mode){
    __shared__ __align__(16) float As[16][68], Bs[16][68];
    if (mode==1) A = g_msg;
    float* C = mode==1 ? g_o : g_v;
    int t=threadIdx.x, i0=blockIdx.x*64, c0=blockIdx.y*64;
    int tx=t&15, ty=t>>4, r=t>>2, k4=(t&3)*4;
    float acc[4][4]={};
    for (int k0=0;k0<256;k0+=16){
        float4 a=*(const float4*)(A+(size_t)(i0+r)*256+k0+k4);
        As[k4+0][r]=a.x; As[k4+1][r]=a.y; As[k4+2][r]=a.z; As[k4+3][r]=a.w;
        float4 b=*(const float4*)(B+(size_t)(c0+r)*256+k0+k4);
        Bs[k4+0][r]=b.x; Bs[k4+1][r]=b.y; Bs[k4+2][r]=b.z; Bs[k4+3][r]=b.w;
        __syncthreads();
        #pragma unroll
        for (int kk=0;kk<16;kk++){
            float4 av=*(const float4*)&As[kk][ty*4];
            float4 bw=*(const float4*)&Bs[kk][tx*4];
            float avv[4]={av.x,av.y,av.z,av.w}, bww[4]={bw.x,bw.y,bw.z,bw.w};
            #pragma unroll
            for (int q=0;q<4;q++)
                #pragma unroll
                for (int p=0;p<4;p++) acc[q][p]=fmaf(avv[q],bww[p],acc[q][p]);
        }
        __syncthreads();
    }
    for (int q=0;q<4;q++){
        int c=c0+tx*4;
        float4 o=make_float4(acc[q][0]+bias[c],acc[q][1]+bias[c+1],acc[q][2]+bias[c+2],acc[q][3]+bias[c+3]);
        *(float4*)(C+(size_t)(i0+ty*4+q)*256+c)=o;
    }
}

// A phys: [0,3072)=w (masked, bf16), [3072,6144)=w^2. j split 2-way (grid.y).
__global__ __launch_bounds__(256) void kpow(const float* w){
    int t=threadIdx.x;
    float c1h[4]={g_c1[0],g_c1[1],g_c1[2],g_c1[3]};
    int i = blockIdx.x*8 + (t>>5), l = t&31;
    int jbase = blockIdx.y*1536;
    const float* wr = w + (size_t)i*NN + jbase;
    __nv_bfloat16* Ar = g_A + (size_t)i*KK + jbase;
    float D0=0,D1=0,D2=0,D3=0;
    #pragma unroll 2
    for (int k=0;k<12;k++){
        int j = k*128 + l*4;
        float4 wv = *(const float4*)(wr+j);
        float xs[4]={wv.x,wv.y,wv.z,wv.w};
        __nv_bfloat16 hi[4], sq[4];
        #pragma unroll
        for (int e=0;e<4;e++){
            float x = xs[e]; bool mk = x>0.f;
            float a = mk? x:0.f;
            hi[e]=__float2bfloat16_rn(a);
            sq[e]=__float2bfloat16_rn(a*x);
            float4 er = __ldg((const float4*)(g_ek+(size_t)(jbase+j+e)*4));
            if (mk){
                D0 = fmaf(x, c1h[0]*er.x, D0+er.x);
                D1 = fmaf(x, c1h[1]*er.y, D1+er.y);
                D2 = fmaf(x, c1h[2]*er.z, D2+er.z);
                D3 = fmaf(x, c1h[3]*er.w, D3+er.w);
            }
        }
        *(uint2*)(Ar+j)      = *(uint2*)hi;
        *(uint2*)(Ar+3072+j) = *(uint2*)sq;
    }
    for (int o=16;o;o>>=1){
        D0+=__shfl_xor_sync(~0u,D0,o); D1+=__shfl_xor_sync(~0u,D1,o);
        D2+=__shfl_xor_sync(~0u,D2,o); D3+=__shfl_xor_sync(~0u,D3,o);
    }
    if (l==0) *(float4*)(g_Dp+((size_t)blockIdx.y*NN+i)*4)=make_float4(D0,D1,D2,D3);
}

// Bt[c]: [0,3072)=V1=ek*v, [3072,6144)=V2=c1*V1
__global__ __launch_bounds__(256) void kbuild(){
    __shared__ __align__(16) float vs[64][68];
    __shared__ __align__(16) float es[64][4];
    int t=threadIdx.x, j0=blockIdx.x*64, c0=blockIdx.y*64;
    #pragma unroll
    for (int r=0;r<4;r++){
        int idx=t+r*256, row=idx>>4, col=(idx&15)*4;
        *(float4*)&vs[row][col] = *(const float4*)(g_v+(size_t)(j0+row)*256+c0+col);
    }
    if (t<64) *(float4*)es[t] = *(const float4*)(g_ek+(size_t)(j0+t)*4);
    __syncthreads();
    int cl=t>>2, jq=t&3, c=c0+cl, h=c>>6;
    float c1h=g_c1[h];
    __nv_bfloat16 bh[16], b2[16];
    #pragma unroll
    for (int jj=0;jj<16;jj++){
        int jl=jq*16+jj;
        float V1 = es[jl][h]*vs[jl][cl];
        bh[jj]=__float2bfloat16_rn(V1);
        b2[jj]=__float2bfloat16_rn(c1h*V1);
    }
    __nv_bfloat16* Br = g_Bt + (size_t)c*KK + j0 + jq*16;
    *(uint4*)(Br)      = *(uint4*)(bh);  *(uint4*)(Br+8)      = *(uint4*)(bh+8);
    *(uint4*)(Br+3072) = *(uint4*)(b2);  *(uint4*)(Br+3072+8) = *(uint4*)(b2+8);
}

// bf16 HMMA GEMM, 4-stage cp.async pipeline (dynamic smem, 80KB)
__global__ __launch_bounds__(256,2) void kmma(){
    extern __shared__ __align__(16) char smx[];
    const int tid=threadIdx.x, lane=tid&31, wid=tid>>5;
    const int wm=wid&3, wn=wid>>2;
    const int i0=blockIdx.x*128, c0=blockIdx.y*128, sl=blockIdx.z;
    float acc[2][8][4];
    #pragma unroll
    for(int a=0;a<2;a++)
        #pragma unroll
        for(int b=0;b<8;b++)
            #pragma unroll
            for(int c=0;c<4;c++) acc[a][b][c]=0.f;
    const int r4 = tid>>2, q4 = (tid&3)*8;
    const int arow = lane&15, akh = (lane>>4)*8;
    const int brow = (lane&7) + ((lane>>4)&1)*8, bkh = ((lane>>3)&1)*8;
    auto ld_stage=[&](int buf,int st){
        int kl = sl*1024 + st*32;
        char* base = smx + buf*STG_BYTES;
        #pragma unroll
        for(int hh=0;hh<2;hh++){
            int row=r4+hh*64;
            uint32_t da = s2u(base + (row*40+q4)*2);
            const void* sa = g_A + (size_t)(i0+row)*KK + kl + q4;
            asm volatile("cp.async.cg.shared.global [%0],[%1],16;"::"r"(da),"l"(sa));
            uint32_t db = s2u(base + 10240 + (row*40+q4)*2);
            const void* sb = g_Bt + (size_t)(c0+row)*KK + kl + q4;
            asm volatile("cp.async.cg.shared.global [%0],[%1],16;"::"r"(db),"l"(sb));
        }
        asm volatile("cp.async.commit_group;");
    };
    ld_stage(0,0); ld_stage(1,1); ld_stage(2,2);
    for(int st=0;st<32;st++){
        int buf=st&3;
        if(st+3<32) ld_stage((st+3)&3, st+3);
        if(st<29) waitg<3>();
        else if(st==29) waitg<2>();
        else if(st==30) waitg<1>();
        else waitg<0>();
        __syncthreads();
        char* base = smx + buf*STG_BYTES;
        uint32_t abase = s2u(base), bbase = s2u(base+10240);
        #pragma unroll
        for(int kk=0;kk<2;kk++){
            uint32_t af[2][4], bf[4][4];
            #pragma unroll
            for(int mb=0;mb<2;mb++)
                ldm4(af[mb], abase + (uint32_t)((wm*32+mb*16+arow)*40 + kk*16 + akh)*2u);
            #pragma unroll
            for(int nb=0;nb<4;nb++)
                ldm4(bf[nb], bbase + (uint32_t)((wn*64+nb*16+brow)*40 + kk*16 + bkh)*2u);
            #pragma unroll
            for(int mb=0;mb<2;mb++)
                #pragma unroll
                for(int nb=0;nb<4;nb++){
                    mma16816(acc[mb][nb*2],   af[mb], bf[nb][0], bf[nb][1]);
                    mma16816(acc[mb][nb*2+1], af[mb], bf[nb][2], bf[nb][3]);
                }
        }
        __syncthreads();
    }
    #pragma unroll
    for(int mb=0;mb<2;mb++){
        int ri = i0 + wm*32 + mb*16 + (lane>>2);
        #pragma unroll
        for(int nbk=0;nbk<8;nbk++){
            int c = c0 + wn*64 + nbk*8 + (lane&3)*2;
            *(float2*)(g_part + ((size_t)sl*NN + ri)*256 + c)   = make_float2(acc[mb][nbk][0],acc[mb][nbk][1]);
            *(float2*)(g_part + ((size_t)sl*NN + ri+8)*256 + c) = make_float2(acc[mb][nbk][2],acc[mb][nbk][3]);
        }
    }
}

__global__ void kreduce(){
    int i=blockIdx.x, c=threadIdx.x, h=c>>6;
    float s=0.f;
    for (int sl=0;sl<NSL;sl++) s += g_part[((size_t)sl*NN+i)*256+c];
    float D = g_Dp[i*4+h] + g_Dp[(NN+i)*4+h];
    g_msg[(size_t)i*256+c] = s / D;
}

__global__ void kln(const float* hm, const float* gamma, const float* beta, float* out){
    __shared__ float red[8];
    int i=blockIdx.x, t=threadIdx.x;
    float x = hm[(size_t)i*256+t] + g_o[(size_t)i*256+t];
    float v=x;
    for (int o=16;o;o>>=1) v+=__shfl_xor_sync(~0u,v,o);
    if ((t&31)==0) red[t>>5]=v;
    __syncthreads();
    if (t==0){ float s=0; for(int k=0;k<8;k++)s+=red[k]; red[0]=s*(1.f/256.f); }
    __syncthreads();
    float mu=red[0], d=x-mu;
    __syncthreads();
    v=d*d;
    for (int o=16;o;o>>=1) v+=__shfl_xor_sync(~0u,v,o);
    if ((t&31)==0) red[t>>5]=v;
    __syncthreads();
    if (t==0){ float s=0; for(int k=0;k<8;k++)s+=red[k]; red[0]=s*(1.f/256.f); }
    __syncthreads();
    out[(size_t)i*256+t] = gamma[t]*d*rsqrtf(red[0]+1e-5f)+beta[t];
}

extern "C" void kernel_launch(void* const* d_in, const int* in_sizes, int n_in,
                              void* d_out, int out_size){
    const float *hm=(const float*)d_in[0], *w=(const float*)d_in[1],
        *Wk=(const float*)d_in[4], *bk=(const float*)d_in[5],
        *Wv=(const float*)d_in[6], *bv=(const float*)d_in[7],
        *Wew=(const float*)d_in[8], *u=(const float*)d_in[10],
        *Wo=(const float*)d_in[11], *bo=(const float*)d_in[12],
        *gamma=(const float*)d_in[13], *beta=(const float*)d_in[14];
    cudaFuncSetAttribute(kmma, cudaFuncAttributeMaxDynamicSharedMemorySize, 4*STG_BYTES);
    kprep0<<<4,256>>>(Wk,bk,Wew,u);
    kprep1<<<48,256>>>(hm);
    kgemm<<<dim3(48,4),256>>>(hm,Wv,bv,0);
    kpow<<<dim3(384,2),256>>>(w);
    kbuild<<<dim3(48,4),256>>>();
    kmma<<<dim3(24,2,NSL),256,4*STG_BYTES>>>();
    kreduce<<<NN,256>>>();
    kgemm<<<dim3(48,4),256>>>(nullptr,Wo,bo,1);
    kln<<<NN,256>>>(hm,gamma,beta,(float*)d_out);
}

// round 17
// speedup vs baseline: 2.2298x; 1.0280x over previous
#include <cuda_runtime.h>
#include <cuda_bf16.h>
#include <cstdint>
#define NN 3072
#define KK 6144
#define NSL 6
#define STG_BYTES 20480

__device__ __align__(256) float g_wkeff[4*256];
__device__ float g_c1[4], g_skb[4];
__device__ __align__(256) float g_ek[NN*4];
__device__ __align__(256) float g_v[NN*256];
__device__ __align__(256) __nv_bfloat16 g_A[(size_t)NN*KK];
__device__ __align__(256) __nv_bfloat16 g_Bt[(size_t)256*KK];
__device__ __align__(256) float g_part[(size_t)NSL*NN*256];
__device__ __align__(256) float g_Dp[2*NN*4];
__device__ __align__(256) float g_msg[NN*256];
__device__ __align__(256) float g_o[NN*256];

__device__ __forceinline__ uint32_t s2u(const void* p){
    uint32_t a; asm("{.reg .u64 t; cvta.to.shared.u64 t, %1; cvt.u32.u64 %0, t;}":"=r"(a):"l"(p)); return a;
}
__device__ __forceinline__ void ldm4(uint32_t* r, uint32_t a){
    asm volatile("ldmatrix.sync.aligned.m8n8.x4.shared.b16 {%0,%1,%2,%3},[%4];"
        :"=r"(r[0]),"=r"(r[1]),"=r"(r[2]),"=r"(r[3]):"r"(a));
}
__device__ __forceinline__ void mma16816(float* c, const uint32_t* a, uint32_t b0, uint32_t b1){
    asm volatile("mma.sync.aligned.m16n8k16.row.col.f32.bf16.bf16.f32 "
        "{%0,%1,%2,%3},{%4,%5,%6,%7},{%8,%9},{%0,%1,%2,%3};"
        :"+f"(c[0]),"+f"(c[1]),"+f"(c[2]),"+f"(c[3])
        :"r"(a[0]),"r"(a[1]),"r"(a[2]),"r"(a[3]),"r"(b0),"r"(b1));
}
template<int N> __device__ __forceinline__ void waitg(){
    asm volatile("cp.async.wait_group %0;"::"n"(N):"memory");
}

// grid 4: block = head h
__global__ void kprep0(const float* Wk, const float* bk, const float* Wew, const float* u){
    int m = threadIdx.x, h = blockIdx.x;
    float s=0.f;
    for (int d=0;d<64;d++) s += u[h*136+64+d]*Wk[(h*64+d)*256+m];
    g_wkeff[h*256+m]=s;
    if (m==0){
        float c=0.f, sb=0.f;
        for (int d=0;d<8;d++)  c  += Wew[h*8+d]*u[h*136+128+d];
        for (int d=0;d<64;d++) sb += bk[h*64+d]*u[h*136+64+d];
        g_c1[h]=c; g_skb[h]=sb;
    }
}

// grid 96: 32 rows/block, dot split 2-way per thread pair
__global__ void kprep1(const float* hm){
    __shared__ __align__(16) float wk[1024];
    int t = threadIdx.x;
    ((float4*)wk)[t] = ((const float4*)g_wkeff)[t];
    __syncthreads();
    int j = blockIdx.x*32 + (t>>3);
    int sub = t&7, ch = sub>>1, half = sub&1;
    const float* hr = hm + (size_t)j*256 + half*128;
    const float* w = wk + ch*256 + half*128;
    float s = half? 0.f : g_skb[ch];
    #pragma unroll 8
    for (int m=0;m<128;m+=4){
        float4 hv = *(const float4*)(hr+m);
        s += hv.x*w[m]+hv.y*w[m+1]+hv.z*w[m+2]+hv.w*w[m+3];
    }
    s += __shfl_xor_sync(~0u, s, 1);
    if (half==0) g_ek[j*4+ch] = expf(s);
}

// C = A@B^T + bias; smem transposed [kk][row] -> LDS.128 reads
__global__ __launch_bounds__(256) void kgemm(const float* A, const float* B, const float* bias, int mode){
    __shared__ __align__(16) float As[16][68], Bs[16][68];
    if (mode==1) A = g_msg;
    float* C = mode==1 ? g_o : g_v;
    int t=threadIdx.x, i0=blockIdx.x*64, c0=blockIdx.y*64;
    int tx=t&15, ty=t>>4, r=t>>2, k4=(t&3)*4;
    float acc[4][4]={};
    for (int k0=0;k0<256;k0+=16){
        float4 a=*(const float4*)(A+(size_t)(i0+r)*256+k0+k4);
        As[k4+0][r]=a.x; As[k4+1][r]=a.y; As[k4+2][r]=a.z; As[k4+3][r]=a.w;
        float4 b=*(const float4*)(B+(size_t)(c0+r)*256+k0+k4);
        Bs[k4+0][r]=b.x; Bs[k4+1][r]=b.y; Bs[k4+2][r]=b.z; Bs[k4+3][r]=b.w;
        __syncthreads();
        #pragma unroll
        for (int kk=0;kk<16;kk++){
            float4 av=*(const float4*)&As[kk][ty*4];
            float4 bw=*(const float4*)&Bs[kk][tx*4];
            float avv[4]={av.x,av.y,av.z,av.w}, bww[4]={bw.x,bw.y,bw.z,bw.w};
            #pragma unroll
            for (int q=0;q<4;q++)
                #pragma unroll
                for (int p=0;p<4;p++) acc[q][p]=fmaf(avv[q],bww[p],acc[q][p]);
        }
        __syncthreads();
    }
    for (int q=0;q<4;q++){
        int c=c0+tx*4;
        float4 o=make_float4(acc[q][0]+bias[c],acc[q][1]+bias[c+1],acc[q][2]+bias[c+2],acc[q][3]+bias[c+3]);
        *(float4*)(C+(size_t)(i0+ty*4+q)*256+c)=o;
    }
}

// A phys: [0,3072)=w (masked, bf16), [3072,6144)=w^2.
// Register-tiled: thread owns j-quad, iterates 4 rows -> ek loaded once per 4 rows.
__global__ __launch_bounds__(256) void kpow(const float* w){
    int t=threadIdx.x;
    float c1h[4]={g_c1[0],g_c1[1],g_c1[2],g_c1[3]};
    int i0 = blockIdx.x*8;
    int rg = t>>7, tq = t&127;
    int jbase = blockIdx.y*1536;
    float D[4][4];
    #pragma unroll
    for(int r=0;r<4;r++)
        #pragma unroll
        for(int h=0;h<4;h++) D[r][h]=0.f;
    for (int k=0;k<3;k++){
        int j = jbase + k*512 + tq*4;
        float4 es[4];
        es[0]=__ldg((const float4*)(g_ek+(size_t)j*4));
        es[1]=__ldg((const float4*)(g_ek+(size_t)(j+1)*4));
        es[2]=__ldg((const float4*)(g_ek+(size_t)(j+2)*4));
        es[3]=__ldg((const float4*)(g_ek+(size_t)(j+3)*4));
        #pragma unroll
        for(int r=0;r<4;r++){
            int i = i0 + rg*4 + r;
            float4 wv = *(const float4*)(w + (size_t)i*NN + j);
            float xs[4]={wv.x,wv.y,wv.z,wv.w};
            __nv_bfloat16 hi[4], sq[4];
            #pragma unroll
            for(int e=0;e<4;e++){
                float x=xs[e]; bool mk = x>0.f;
                float a = mk? x:0.f;
                hi[e]=__float2bfloat16_rn(a);
                sq[e]=__float2bfloat16_rn(a*x);
                if(mk){
                    D[r][0] = fmaf(x, c1h[0]*es[e].x, D[r][0]+es[e].x);
                    D[r][1] = fmaf(x, c1h[1]*es[e].y, D[r][1]+es[e].y);
                    D[r][2] = fmaf(x, c1h[2]*es[e].z, D[r][2]+es[e].z);
                    D[r][3] = fmaf(x, c1h[3]*es[e].w, D[r][3]+es[e].w);
                }
            }
            __nv_bfloat16* Ar = g_A + (size_t)i*KK + j;
            *(uint2*)Ar        = *(uint2*)hi;
            *(uint2*)(Ar+3072) = *(uint2*)sq;
        }
    }
    __shared__ float sD[8][16];
    int lane=t&31, wd=t>>5;
    #pragma unroll
    for(int r=0;r<4;r++)
        #pragma unroll
        for(int h=0;h<4;h++){
            float v=D[r][h];
            for(int o=16;o;o>>=1) v+=__shfl_xor_sync(~0u,v,o);
            if(lane==0) sD[wd][r*4+h]=v;
        }
    __syncthreads();
    if (t<32){
        int rg2 = t>>4, idx = t&15;
        float s = sD[rg2*4+0][idx]+sD[rg2*4+1][idx]+sD[rg2*4+2][idx]+sD[rg2*4+3][idx];
        int i = i0 + rg2*4 + (idx>>2);
        g_Dp[((size_t)blockIdx.y*NN + i)*4 + (idx&3)] = s;
    }
}

// Bt[c]: [0,3072)=V1=ek*v, [3072,6144)=V2=c1*V1
__global__ __launch_bounds__(256) void kbuild(){
    __shared__ __align__(16) float vs[64][68];
    __shared__ __align__(16) float es[64][4];
    int t=threadIdx.x, j0=blockIdx.x*64, c0=blockIdx.y*64;
    #pragma unroll
    for (int r=0;r<4;r++){
        int idx=t+r*256, row=idx>>4, col=(idx&15)*4;
        *(float4*)&vs[row][col] = *(const float4*)(g_v+(size_t)(j0+row)*256+c0+col);
    }
    if (t<64) *(float4*)es[t] = *(const float4*)(g_ek+(size_t)(j0+t)*4);
    __syncthreads();
    int cl=t>>2, jq=t&3, c=c0+cl, h=c>>6;
    float c1h=g_c1[h];
    __nv_bfloat16 bh[16], b2[16];
    #pragma unroll
    for (int jj=0;jj<16;jj++){
        int jl=jq*16+jj;
        float V1 = es[jl][h]*vs[jl][cl];
        bh[jj]=__float2bfloat16_rn(V1);
        b2[jj]=__float2bfloat16_rn(c1h*V1);
    }
    __nv_bfloat16* Br = g_Bt + (size_t)c*KK + j0 + jq*16;
    *(uint4*)(Br)      = *(uint4*)(bh);  *(uint4*)(Br+8)      = *(uint4*)(bh+8);
    *(uint4*)(Br+3072) = *(uint4*)(b2);  *(uint4*)(Br+3072+8) = *(uint4*)(b2+8);
}

// bf16 HMMA GEMM, 4-stage cp.async pipeline (dynamic smem, 80KB)
__global__ __launch_bounds__(256,2) void kmma(){
    extern __shared__ __align__(16) char smx[];
    const int tid=threadIdx.x, lane=tid&31, wid=tid>>5;
    const int wm=wid&3, wn=wid>>2;
    const int i0=blockIdx.x*128, c0=blockIdx.y*128, sl=blockIdx.z;
    float acc[2][8][4];
    #pragma unroll
    for(int a=0;a<2;a++)
        #pragma unroll
        for(int b=0;b<8;b++)
            #pragma unroll
            for(int c=0;c<4;c++) acc[a][b][c]=0.f;
    const int r4 = tid>>2, q4 = (tid&3)*8;
    const int arow = lane&15, akh = (lane>>4)*8;
    const int brow = (lane&7) + ((lane>>4)&1)*8, bkh = ((lane>>3)&1)*8;
    auto ld_stage=[&](int buf,int st){
        int kl = sl*1024 + st*32;
        char* base = smx + buf*STG_BYTES;
        #pragma unroll
        for(int hh=0;hh<2;hh++){
            int row=r4+hh*64;
            uint32_t da = s2u(base + (row*40+q4)*2);
            const void* sa = g_A + (size_t)(i0+row)*KK + kl + q4;
            asm volatile("cp.async.cg.shared.global [%0],[%1],16;"::"r"(da),"l"(sa));
            uint32_t db = s2u(base + 10240 + (row*40+q4)*2);
            const void* sb = g_Bt + (size_t)(c0+row)*KK + kl + q4;
            asm volatile("cp.async.cg.shared.global [%0],[%1],16;"::"r"(db),"l"(sb));
        }
        asm volatile("cp.async.commit_group;");
    };
    ld_stage(0,0); ld_stage(1,1); ld_stage(2,2);
    for(int st=0;st<32;st++){
        int buf=st&3;
        if(st+3<32) ld_stage((st+3)&3, st+3);
        if(st<29) waitg<3>();
        else if(st==29) waitg<2>();
        else if(st==30) waitg<1>();
        else waitg<0>();
        __syncthreads();
        char* base = smx + buf*STG_BYTES;
        uint32_t abase = s2u(base), bbase = s2u(base+10240);
        #pragma unroll
        for(int kk=0;kk<2;kk++){
            uint32_t af[2][4], bf[4][4];
            #pragma unroll
            for(int mb=0;mb<2;mb++)
                ldm4(af[mb], abase + (uint32_t)((wm*32+mb*16+arow)*40 + kk*16 + akh)*2u);
            #pragma unroll
            for(int nb=0;nb<4;nb++)
                ldm4(bf[nb], bbase + (uint32_t)((wn*64+nb*16+brow)*40 + kk*16 + bkh)*2u);
            #pragma unroll
            for(int mb=0;mb<2;mb++)
                #pragma unroll
                for(int nb=0;nb<4;nb++){
                    mma16816(acc[mb][nb*2],   af[mb], bf[nb][0], bf[nb][1]);
                    mma16816(acc[mb][nb*2+1], af[mb], bf[nb][2], bf[nb][3]);
                }
        }
        __syncthreads();
    }
    #pragma unroll
    for(int mb=0;mb<2;mb++){
        int ri = i0 + wm*32 + mb*16 + (lane>>2);
        #pragma unroll
        for(int nbk=0;nbk<8;nbk++){
            int c = c0 + wn*64 + nbk*8 + (lane&3)*2;
            *(float2*)(g_part + ((size_t)sl*NN + ri)*256 + c)   = make_float2(acc[mb][nbk][0],acc[mb][nbk][1]);
            *(float2*)(g_part + ((size_t)sl*NN + ri+8)*256 + c) = make_float2(acc[mb][nbk][2],acc[mb][nbk][3]);
        }
    }
}

__global__ void kreduce(){
    int i=blockIdx.x, c=threadIdx.x, h=c>>6;
    float s=0.f;
    for (int sl=0;sl<NSL;sl++) s += g_part[((size_t)sl*NN+i)*256+c];
    float D = g_Dp[i*4+h] + g_Dp[(NN+i)*4+h];
    g_msg[(size_t)i*256+c] = s / D;
}

__global__ void kln(const float* hm, const float* gamma, const float* beta, float* out){
    __shared__ float red[8];
    int i=blockIdx.x, t=threadIdx.x;
    float x = hm[(size_t)i*256+t] + g_o[(size_t)i*256+t];
    float v=x;
    for (int o=16;o;o>>=1) v+=__shfl_xor_sync(~0u,v,o);
    if ((t&31)==0) red[t>>5]=v;
    __syncthreads();
    if (t==0){ float s=0; for(int k=0;k<8;k++)s+=red[k]; red[0]=s*(1.f/256.f); }
    __syncthreads();
    float mu=red[0], d=x-mu;
    __syncthreads();
    v=d*d;
    for (int o=16;o;o>>=1) v+=__shfl_xor_sync(~0u,v,o);
    if ((t&31)==0) red[t>>5]=v;
    __syncthreads();
    if (t==0){ float s=0; for(int k=0;k<8;k++)s+=red[k]; red[0]=s*(1.f/256.f); }
    __syncthreads();
    out[(size_t)i*256+t] = gamma[t]*d*rsqrtf(red[0]+1e-5f)+beta[t];
}

extern "C" void kernel_launch(void* const* d_in, const int* in_sizes, int n_in,
                              void* d_out, int out_size){
    const float *hm=(const float*)d_in[0], *w=(const float*)d_in[1],
        *Wk=(const float*)d_in[4], *bk=(const float*)d_in[5],
        *Wv=(const float*)d_in[6], *bv=(const float*)d_in[7],
        *Wew=(const float*)d_in[8], *u=(const float*)d_in[10],
        *Wo=(const float*)d_in[11], *bo=(const float*)d_in[12],
        *gamma=(const float*)d_in[13], *beta=(const float*)d_in[14];
    cudaFuncSetAttribute(kmma, cudaFuncAttributeMaxDynamicSharedMemorySize, 4*STG_BYTES);
    kprep0<<<4,256>>>(Wk,bk,Wew,u);
    kprep1<<<96,256>>>(hm);
    kgemm<<<dim3(48,4),256>>>(hm,Wv,bv,0);
    kpow<<<dim3(384,2),256>>>(w);
    kbuild<<<dim3(48,4),256>>>();
    kmma<<<dim3(24,2,NSL),256,4*STG_BYTES>>>();
    kreduce<<<NN,256>>>();
    kgemm<<<dim3(48,4),256>>>(nullptr,Wo,bo,1);
    kln<<<NN,256>>>(hm,gamma,beta,(float*)d_out);
}